// round 1
// baseline (speedup 1.0000x reference)
#include <cuda_runtime.h>
#include <cuda_bf16.h>

// PositionalEmbedding: out[b, s, d] = sin((start_pos+s) * 10000^(-2d/E)) for even d,
//                                     cos(...) for odd d, E = 1024. Broadcast over b.
// Shapes: B=4, S=8192, D=1024, fp32 out. Input x is never read (output depends
// only on shape), so this is a pure 128 MiB store kernel + cheap transcendental
// compute (8M unique values, each written 4x).

#define PE_B 4
#define PE_S 8192
#define PE_D 1024

// c = -2*log2(10000)/1024 ; r = 2^c = 10000^(-2/1024)
#define PE_C  (-0.025952563241307517f)
#define PE_R  (0.9821718857094753f)

__global__ void __launch_bounds__(256)
pe_kernel(const int* __restrict__ start_pos, float* __restrict__ out)
{
    // one thread -> one float4 (4 consecutive d), written to all 4 batches
    int idx = blockIdx.x * blockDim.x + threadIdx.x;   // 0 .. S*D/4 - 1
    const int SD4 = PE_S * PE_D / 4;                   // 2,097,152
    if (idx >= SD4) return;

    int s  = idx >> 8;          // D/4 = 256 float4 per row
    int d0 = (idx & 255) << 2;  // first of 4 consecutive d, d0 is even

    float pos = (float)(start_pos[0] + s);

    // inv_freq chain: f(d) = 2^(c*d); compute one EX2, then multiply by r.
    float f0 = exp2f(PE_C * (float)d0);
    float f1 = f0 * PE_R;
    float f2 = f1 * PE_R;
    float f3 = f2 * PE_R;

    float4 v;
    v.x = sinf(pos * f0);   // even d -> sin
    v.y = cosf(pos * f1);   // odd  d -> cos
    v.z = sinf(pos * f2);
    v.w = cosf(pos * f3);

    float4* __restrict__ o = (float4*)out;
    o[idx            ] = v;
    o[idx +     SD4  ] = v;
    o[idx + 2 * SD4  ] = v;
    o[idx + 3 * SD4  ] = v;
}

extern "C" void kernel_launch(void* const* d_in, const int* in_sizes, int n_in,
                              void* d_out, int out_size)
{
    (void)in_sizes; (void)n_in; (void)out_size;
    const int* start_pos = (const int*)d_in[1];   // metadata order: x, start_pos
    float* out = (float*)d_out;

    const int total = PE_S * PE_D / 4;            // float4 elements per batch slice
    const int threads = 256;
    const int blocks = (total + threads - 1) / threads;   // 8192
    pe_kernel<<<blocks, threads>>>(start_pos, out);
}